// round 14
// baseline (speedup 1.0000x reference)
#include <cuda_runtime.h>

#define SQS  2.44140625e-4f         // 2^-12: folds 1/sqrt(4096) * (1/sqrt2)^12
#define SCP  5.9604644775390625e-8f // 2^-24 = SQS^2

__device__ __forceinline__ float fsqrt_ap(float x) {
    float r; asm("sqrt.approx.f32 %0, %1;" : "=f"(r) : "f"(x)); return r;
}
__device__ __forceinline__ float frsqrt_ap(float x) {
    float r; asm("rsqrt.approx.f32 %0, %1;" : "=f"(r) : "f"(x)); return r;
}
__device__ __forceinline__ float sx(float v, int m) {
    return __shfl_xor_sync(0xFFFFFFFFu, v, m, 32);
}
// butterfly via FFMA-imm (rt_SMSP=1 vs FADD's 2): a + b and a - b
__device__ __forceinline__ float bp(float a, float b) {
    float r; asm("fma.rn.f32 %0,%1,0f3F800000,%2;" : "=f"(r) : "f"(b), "f"(a)); return r;
}
__device__ __forceinline__ float bm(float a, float b) {
    float r; asm("fma.rn.f32 %0,%1,0fBF800000,%2;" : "=f"(r) : "f"(b), "f"(a)); return r;
}

// Fused gate G_q = CNOT·CRX·(H⊗I) on local bits (LO=control, HI=target).
// H unnormalized (2^-12 amp scale folded into init).
template<int LO, int HI>
__device__ __forceinline__ void step_local(float (&R)[16], float (&I)[16],
                                           float c, float s) {
    constexpr int L0 = 1 << LO, L1 = 1 << HI;
#pragma unroll
    for (int m = 0; m < 16; ++m) {
        if (m & (L0 | L1)) continue;
        const int a = m, b = m | L0, e = m | L1, d = m | L0 | L1;
        float t0;
        t0 = bp(R[a], R[b]); R[b] = bm(R[a], R[b]); R[a] = t0;
        t0 = bp(I[a], I[b]); I[b] = bm(I[a], I[b]); I[a] = t0;
        t0 = bp(R[e], R[d]); R[d] = bm(R[e], R[d]); R[e] = t0;
        t0 = bp(I[e], I[d]); I[d] = bm(I[e], I[d]); I[e] = t0;
        // CRX (s-coef = -i*sin) then CNOT swap on (b,d)
        float xr = fmaf(s,  I[b], c * R[d]);
        float xi = fmaf(-s, R[b], c * I[d]);
        float yr = fmaf(s,  I[d], c * R[b]);
        float yi = fmaf(-s, R[d], c * I[b]);
        R[b] = xr; I[b] = xi; R[d] = yr; I[d] = yi;
    }
}

// Gate with control = local bit 3, target = lane bit (mask M).
// With CNOT: new = s*self + c*partner.  FINAL (q=11, no CNOT): new = c*self + s*partner.
template<bool FINAL>
__device__ __forceinline__ void step_shfl(float (&R)[16], float (&I)[16],
                                          float c, float s, int M) {
#pragma unroll
    for (int m = 0; m < 8; ++m) {      // H on local bit 3
        const int a = m, b = m | 8;
        float t0;
        t0 = bp(R[a], R[b]); R[b] = bm(R[a], R[b]); R[a] = t0;
        t0 = bp(I[a], I[b]); I[b] = bm(I[a], I[b]); I[a] = t0;
    }
#pragma unroll
    for (int m = 8; m < 16; ++m) {     // CRX(+CNOT) across lane bit, control==1
        float mr = R[m], mi = I[m];
        float pr = sx(mr, M), pi = sx(mi, M);
        if (FINAL) {
            R[m] = fmaf(c, mr,  s * pi);
            I[m] = fmaf(c, mi, -s * pr);
        } else {
            R[m] = fmaf(s,  mi, c * pr);
            I[m] = fmaf(-s, mr, c * pi);
        }
    }
}

__global__ void __launch_bounds__(512, 2)
quantum_kernel(const float* __restrict__ x,
               const float* __restrict__ prm,
               float* __restrict__ out) {
    extern __shared__ float2 dbuf[];       // 2 x 32 KB transpose buffers
    __shared__ float2 cs[12];
    __shared__ float4 red4[4];             // per-warp sumsq, 8 floats per row-half

    const int tid = threadIdx.x;
    const int rr  = tid >> 8;              // row-half 0/1
    const int t   = tid & 255;             // intra-row thread id
    const int lane = tid & 31, w = t >> 5; // w = warp index within row-half (0..7)
    float2* __restrict__ buf = dbuf + (rr << 12);
    float*  __restrict__ red = ((float*)red4) + (rr << 3);

    const size_t row = ((size_t)blockIdx.x << 1) | rr;
    const float* __restrict__ xr = x + row * 4096;

    // ---- precomputed swizzled-address bases (sw(i) = i ^ ((i>>4)&30)) ----
    const int PA = (t << 4) ^ (t & 30);                               // A-write
    const int PB = ((t & 15) | ((t >> 4) << 8)) ^ (((t >> 4) & 1) << 4); // B map
    const int PC = t ^ ((t >> 4) & 14);                               // C map

    // load 16 consecutive floats: abs index = t*16 + j (phase-A layout)
    float v[16];
#pragma unroll
    for (int k = 0; k < 4; ++k) {
        float4 q = *reinterpret_cast<const float4*>(xr + t * 16 + k * 4);
        v[4*k] = q.x; v[4*k+1] = q.y; v[4*k+2] = q.z; v[4*k+3] = q.w;
    }
    if (tid < 12) { float th = prm[tid] * 0.5f; cs[tid] = make_float2(cosf(th), sinf(th)); }

    // row reduction: sum of squares
    float ss = 0.f;
#pragma unroll
    for (int j = 0; j < 16; ++j) ss = fmaf(v[j], v[j], ss);
#pragma unroll
    for (int m = 16; m >= 1; m >>= 1) ss += sx(ss, m);
    if (lane == 0) red[w] = ss;
    __syncthreads();
    float4 p0 = ((float4*)red)[0], p1 = ((float4*)red)[1];
    float S = ((p0.x + p0.y) + (p0.z + p0.w)) + ((p1.x + p1.y) + (p1.z + p1.w));
    // nsc folds row norm, state norm (1/64) and the 12 Hadamards' 2^-6
    const float nsc = SQS * frsqrt_ap(S);

    // _to_quantum (pre-scaled): re = x*nsc; im = sgn*sqrt(2^-24 - re^2)
    float R[16], I[16];
#pragma unroll
    for (int j = 0; j < 16; ++j) {
        float xv = v[j];
        float r  = xv * nsc;
        float s  = fsqrt_ap(fmaf(-r, r, SCP));
        R[j] = r;
        I[j] = copysignf(s, xv);
    }

#define LSTEP(Q,LO,HI) { float2 g = cs[Q]; step_local<LO,HI>(R, I, g.x, g.y); }
#define SSTEP(Q,M,F)   { float2 g = cs[Q]; step_shfl<F>(R, I, g.x, g.y, M); }

    // Phase A: q=0,1,2 local on abs (0,1),(1,2),(2,3); q=3 on (3,4): lane bit0
    LSTEP(0, 0, 1) LSTEP(1, 1, 2) LSTEP(2, 2, 3)
    SSTEP(3, 1, false)

    // Transpose A->B write (STS.128, 1 XOR per address)
    {
        float4* b4 = reinterpret_cast<float4*>(buf);
        const int pa1 = PA >> 1;
#pragma unroll
        for (int k = 0; k < 8; ++k) {
            b4[pa1 ^ k] = make_float4(R[2*k], I[2*k], R[2*k+1], I[2*k+1]);
        }
    }
    __syncthreads();
#pragma unroll
    for (int j = 0; j < 16; ++j) {
        float2 a = buf[PB ^ ((j << 4) ^ (j & 14))];
        R[j] = a.x; I[j] = a.y;
    }
    // NO barrier: B->C writes below hit exactly the slots this thread just read.

    // Phase B: q=4,5,6 local on abs (4,5),(5,6),(6,7); q=7 on (7,8): lane bit4
    LSTEP(4, 0, 1) LSTEP(5, 1, 2) LSTEP(6, 2, 3)
    SSTEP(7, 16, false)

    // Transpose B->C (write own slots, barrier, gather)
#pragma unroll
    for (int j = 0; j < 16; ++j)
        buf[PB ^ ((j << 4) ^ (j & 14))] = make_float2(R[j], I[j]);
    __syncthreads();
#pragma unroll
    for (int j = 0; j < 16; ++j) {
        float2 a = buf[PC ^ ((j << 8) ^ ((j & 1) << 4))];
        R[j] = a.x; I[j] = a.y;
    }
    // no trailing barrier: buf dead from here

    // Phase C: q=8,9,10 local on abs (8,9),(9,10),(10,11); q=11 on (11,0): lane bit0, NO CNOT
    LSTEP(8, 0, 1) LSTEP(9, 1, 2) LSTEP(10, 2, 3)
    SSTEP(11, 1, true)

    // output: abs = (j<<8) | t — coalesced 128B per warp per j; scale pre-folded
    float* __restrict__ orow = out + row * 4096;
#pragma unroll
    for (int j = 0; j < 16; ++j) {
        orow[(j << 8) | t] = fmaf(R[j], R[j], I[j] * I[j]);
    }
}

extern "C" void kernel_launch(void* const* d_in, const int* in_sizes, int n_in,
                              void* d_out, int out_size) {
    const float* state  = (const float*)d_in[0];
    const float* params = (const float*)d_in[1];
    float* out = (float*)d_out;
    int rows = in_sizes[0] / 4096;   // 4096 rows

    const size_t smem = 2 * 4096 * sizeof(float2);   // 64 KB dynamic
    cudaFuncSetAttribute(quantum_kernel,
                         cudaFuncAttributeMaxDynamicSharedMemorySize, (int)smem);
    quantum_kernel<<<rows / 2, 512, smem>>>(state, params, out);
}

// round 15
// speedup vs baseline: 1.2152x; 1.2152x over previous
#include <cuda_runtime.h>

#define SQS  2.44140625e-4f         // 2^-12: folds 1/sqrt(4096) * (1/sqrt2)^12
#define SCP  5.9604644775390625e-8f // 2^-24 = SQS^2

__device__ __forceinline__ float fsqrt_ap(float x) {
    float r; asm("sqrt.approx.f32 %0, %1;" : "=f"(r) : "f"(x)); return r;
}
__device__ __forceinline__ float frsqrt_ap(float x) {
    float r; asm("rsqrt.approx.f32 %0, %1;" : "=f"(r) : "f"(x)); return r;
}
__device__ __forceinline__ float sx(float v, int m) {
    return __shfl_xor_sync(0xFFFFFFFFu, v, m, 32);
}
// butterfly via FFMA-imm (rt_SMSP=1 vs FADD's 2): a + b and a - b
__device__ __forceinline__ float bp(float a, float b) {
    float r; asm("fma.rn.f32 %0,%1,0f3F800000,%2;" : "=f"(r) : "f"(b), "f"(a)); return r;
}
__device__ __forceinline__ float bm(float a, float b) {
    float r; asm("fma.rn.f32 %0,%1,0fBF800000,%2;" : "=f"(r) : "f"(b), "f"(a)); return r;
}

// Fused gate G_q = CNOT·CRX·(H⊗I) on local bits (LO=control, HI=target).
// H unnormalized (2^-12 amp scale folded into init).
template<int LO, int HI>
__device__ __forceinline__ void step_local(float (&R)[16], float (&I)[16],
                                           float c, float s) {
    constexpr int L0 = 1 << LO, L1 = 1 << HI;
#pragma unroll
    for (int m = 0; m < 16; ++m) {
        if (m & (L0 | L1)) continue;
        const int a = m, b = m | L0, e = m | L1, d = m | L0 | L1;
        float t0;
        t0 = bp(R[a], R[b]); R[b] = bm(R[a], R[b]); R[a] = t0;
        t0 = bp(I[a], I[b]); I[b] = bm(I[a], I[b]); I[a] = t0;
        t0 = bp(R[e], R[d]); R[d] = bm(R[e], R[d]); R[e] = t0;
        t0 = bp(I[e], I[d]); I[d] = bm(I[e], I[d]); I[e] = t0;
        // CRX (s-coef = -i*sin) then CNOT swap on (b,d)
        float xr = fmaf(s,  I[b], c * R[d]);
        float xi = fmaf(-s, R[b], c * I[d]);
        float yr = fmaf(s,  I[d], c * R[b]);
        float yi = fmaf(-s, R[d], c * I[b]);
        R[b] = xr; I[b] = xi; R[d] = yr; I[d] = yi;
    }
}

// Gate with control = local bit 3, target = lane bit (mask M).
// With CNOT: new = s*self + c*partner.  FINAL (q=11, no CNOT): new = c*self + s*partner.
template<bool FINAL>
__device__ __forceinline__ void step_shfl(float (&R)[16], float (&I)[16],
                                          float c, float s, int M) {
#pragma unroll
    for (int m = 0; m < 8; ++m) {      // H on local bit 3
        const int a = m, b = m | 8;
        float t0;
        t0 = bp(R[a], R[b]); R[b] = bm(R[a], R[b]); R[a] = t0;
        t0 = bp(I[a], I[b]); I[b] = bm(I[a], I[b]); I[a] = t0;
    }
#pragma unroll
    for (int m = 8; m < 16; ++m) {     // CRX(+CNOT) across lane bit, control==1
        float mr = R[m], mi = I[m];
        float pr = sx(mr, M), pi = sx(mi, M);
        if (FINAL) {
            R[m] = fmaf(c, mr,  s * pi);
            I[m] = fmaf(c, mi, -s * pr);
        } else {
            R[m] = fmaf(s,  mi, c * pr);
            I[m] = fmaf(-s, mr, c * pi);
        }
    }
}

__global__ void __launch_bounds__(256, 4)
quantum_kernel(const float* __restrict__ x,
               const float* __restrict__ prm,
               float* __restrict__ out) {
    __shared__ float2 buf[4096];           // 32 KB transpose buffer
    __shared__ float2 cs[12];
    __shared__ float4 red4[2];             // per-warp sumsq (8 floats)

    const int t = threadIdx.x, lane = t & 31, w = t >> 5;
    const float* __restrict__ xr = x + (size_t)blockIdx.x * 4096;

    // ---- precomputed swizzled-address bases (sw(i) = i ^ ((i>>4)&30)) ----
    const int PA = (t << 4) ^ (t & 30);                                  // A-write
    const int PB = ((t & 15) | ((t >> 4) << 8)) ^ (((t >> 4) & 1) << 4); // B map
    const int PC = t ^ ((t >> 4) & 14);                                  // C map

    // load 16 consecutive floats: abs index = t*16 + j (phase-A layout)
    float v[16];
#pragma unroll
    for (int k = 0; k < 4; ++k) {
        float4 q = *reinterpret_cast<const float4*>(xr + t * 16 + k * 4);
        v[4*k] = q.x; v[4*k+1] = q.y; v[4*k+2] = q.z; v[4*k+3] = q.w;
    }
    if (t < 12) { float th = prm[t] * 0.5f; cs[t] = make_float2(cosf(th), sinf(th)); }

    // row reduction: sum of squares
    float ss = 0.f;
#pragma unroll
    for (int j = 0; j < 16; ++j) ss = fmaf(v[j], v[j], ss);
#pragma unroll
    for (int m = 16; m >= 1; m >>= 1) ss += sx(ss, m);
    if (lane == 0) ((float*)red4)[w] = ss;
    __syncthreads();
    float4 p0 = red4[0], p1 = red4[1];
    float S = ((p0.x + p0.y) + (p0.z + p0.w)) + ((p1.x + p1.y) + (p1.z + p1.w));
    // nsc folds row norm, state norm (1/64) and the 12 Hadamards' 2^-6
    const float nsc = SQS * frsqrt_ap(S);

    // _to_quantum (pre-scaled): re = x*nsc; im = sgn*sqrt(2^-24 - re^2)
    float R[16], I[16];
#pragma unroll
    for (int j = 0; j < 16; ++j) {
        float xv = v[j];
        float r  = xv * nsc;
        float s  = fsqrt_ap(fmaf(-r, r, SCP));
        R[j] = r;
        I[j] = copysignf(s, xv);
    }

#define LSTEP(Q,LO,HI) { float2 g = cs[Q]; step_local<LO,HI>(R, I, g.x, g.y); }
#define SSTEP(Q,M,F)   { float2 g = cs[Q]; step_shfl<F>(R, I, g.x, g.y, M); }

    // Phase A: q=0,1,2 local on abs (0,1),(1,2),(2,3); q=3 on (3,4): lane bit0
    LSTEP(0, 0, 1) LSTEP(1, 1, 2) LSTEP(2, 2, 3)
    SSTEP(3, 1, false)

    // Transpose A->B write (STS.128, 1 XOR per address)
    {
        float4* b4 = reinterpret_cast<float4*>(buf);
        const int pa1 = PA >> 1;
#pragma unroll
        for (int k = 0; k < 8; ++k) {
            b4[pa1 ^ k] = make_float4(R[2*k], I[2*k], R[2*k+1], I[2*k+1]);
        }
    }
    __syncthreads();
#pragma unroll
    for (int j = 0; j < 16; ++j) {
        float2 a = buf[PB ^ ((j << 4) ^ (j & 14))];
        R[j] = a.x; I[j] = a.y;
    }
    // NO barrier: B->C writes below hit exactly the slots this thread just read.

    // Phase B: q=4,5,6 local on abs (4,5),(5,6),(6,7); q=7 on (7,8): lane bit4
    LSTEP(4, 0, 1) LSTEP(5, 1, 2) LSTEP(6, 2, 3)
    SSTEP(7, 16, false)

    // Transpose B->C (write own slots, barrier, gather)
#pragma unroll
    for (int j = 0; j < 16; ++j)
        buf[PB ^ ((j << 4) ^ (j & 14))] = make_float2(R[j], I[j]);
    __syncthreads();
#pragma unroll
    for (int j = 0; j < 16; ++j) {
        float2 a = buf[PC ^ ((j << 8) ^ ((j & 1) << 4))];
        R[j] = a.x; I[j] = a.y;
    }
    // no trailing barrier: buf dead from here

    // Phase C: q=8,9,10 local on abs (8,9),(9,10),(10,11); q=11 on (11,0): lane bit0, NO CNOT
    LSTEP(8, 0, 1) LSTEP(9, 1, 2) LSTEP(10, 2, 3)
    SSTEP(11, 1, true)

    // output: abs = (j<<8) | t — coalesced 128B per warp per j; scale pre-folded
    float* __restrict__ orow = out + (size_t)blockIdx.x * 4096;
#pragma unroll
    for (int j = 0; j < 16; ++j) {
        orow[(j << 8) | t] = fmaf(R[j], R[j], I[j] * I[j]);
    }
}

extern "C" void kernel_launch(void* const* d_in, const int* in_sizes, int n_in,
                              void* d_out, int out_size) {
    const float* state  = (const float*)d_in[0];
    const float* params = (const float*)d_in[1];
    float* out = (float*)d_out;
    int rows = in_sizes[0] / 4096;   // 4096 rows
    quantum_kernel<<<rows, 256>>>(state, params, out);
}